// round 1
// baseline (speedup 1.0000x reference)
#include <cuda_runtime.h>

// Problem constants (fixed by dataset): B=4, M=256 preds, N=192 targets.
#define BB 4
#define MM 256
#define NT 192
#define MAT (MM * MM)

// Scratch (static __device__ — no allocations allowed)
__device__ float g_cost[BB * MAT];
__device__ float g_score[BB * MAT];
__device__ float g_box[BB * MAT];

// ---------------------------------------------------------------------------
// Kernel 1: cost matrices. One thread per (b, m, n_full) with n_full in [0,256)
// ---------------------------------------------------------------------------
__device__ __forceinline__ void box_corners(const float* __restrict__ box,
                                            float* X, float* Y) {
    const float cx = box[0], cy = box[1], w = box[2], h = box[3], th = box[4];
    const float c = cosf(th), s = sinf(th);
    const float hw = 0.5f * w, hh = 0.5f * h;
    const float dx[4] = {-hw, hw, hw, -hw};
    const float dy[4] = {-hh, -hh, hh, hh};
#pragma unroll
    for (int k = 0; k < 4; k++) {
        X[k] = cx + dx[k] * c - dy[k] * s;
        Y[k] = cy + dx[k] * s + dy[k] * c;
    }
}

__global__ void cost_kernel(const float* __restrict__ pbox,
                            const float* __restrict__ pscore,
                            const float* __restrict__ tbox,
                            const float* __restrict__ tscore) {
    const int idx = blockIdx.x * 256 + threadIdx.x;
    if (idx >= BB * MAT) return;
    const int n = idx & (MM - 1);
    const int m = (idx >> 8) & (MM - 1);
    const int b = idx >> 16;

    if (n >= NT) {  // zero padding columns
        g_cost[idx] = 0.f; g_score[idx] = 0.f; g_box[idx] = 0.f;
        return;
    }

    const float* bp = pbox + (b * MM + m) * 5;   // pred box
    const float* bt = tbox + (b * NT + n) * 5;   // target box

    float cpx[4], cpy[4], ctx_[4], cty_[4];
    box_corners(bp, cpx, cpy);   // pred corners (polygon to clip)
    box_corners(bt, ctx_, cty_); // target corners (clip edges)

    // Sutherland-Hodgman: clip pred quad by 4 target edges (keep left side)
    float px[8], py[8], qx[8], qy[8];
    int cnt = 4;
#pragma unroll
    for (int k = 0; k < 4; k++) { px[k] = cpx[k]; py[k] = cpy[k]; }

    for (int e = 0; e < 4; e++) {
        const float ax = ctx_[e], ay = cty_[e];
        const float bx = ctx_[(e + 1) & 3], by = cty_[(e + 1) & 3];
        const float dx = bx - ax, dy = by - ay;
        int m2 = 0;
        for (int k = 0; k < cnt; k++) {
            const int kn = (k + 1 == cnt) ? 0 : k + 1;
            const float cxk = px[k], cyk = py[k];
            const float nxk = px[kn], nyk = py[kn];
            const float s_cur = dx * (cyk - ay) - dy * (cxk - ax);
            const float s_nxt = dx * (nyk - ay) - dy * (nxk - ax);
            const bool in_cur = (s_cur >= 0.f);
            const bool in_nxt = (s_nxt >= 0.f);
            if (in_cur) { qx[m2] = cxk; qy[m2] = cyk; m2++; }
            if (in_cur != in_nxt) {
                float den = s_cur - s_nxt;
                if (fabsf(den) <= 1e-9f) den = 1e-9f;
                const float t = s_cur / den;
                qx[m2] = cxk + t * (nxk - cxk);
                qy[m2] = cyk + t * (nyk - cyk);
                m2++;
            }
        }
        cnt = m2;
        for (int k = 0; k < cnt; k++) { px[k] = qx[k]; py[k] = qy[k]; }
    }

    float acc = 0.f;
    for (int k = 0; k < cnt; k++) {
        const int kn = (k + 1 == cnt) ? 0 : k + 1;
        acc += px[k] * py[kn] - px[kn] * py[k];
    }
    const float inter = 0.5f * fabsf(acc);

    const float uni = bt[2] * bt[3] + bp[2] * bp[3] - inter;

    float xmin = cpx[0], xmax = cpx[0], ymin = cpy[0], ymax = cpy[0];
#pragma unroll
    for (int k = 0; k < 4; k++) {
        xmin = fminf(xmin, cpx[k]); xmax = fmaxf(xmax, cpx[k]);
        ymin = fminf(ymin, cpy[k]); ymax = fmaxf(ymax, cpy[k]);
        xmin = fminf(xmin, ctx_[k]); xmax = fmaxf(xmax, ctx_[k]);
        ymin = fminf(ymin, cty_[k]); ymax = fmaxf(ymax, cty_[k]);
    }
    const float enc = (xmax - xmin) * (ymax - ymin);
    const float giou = inter / uni - (enc - uni) / enc;
    const float bcost = 1.f - giou;

    const float sc = fmaxf(0.f, tscore[b * NT + n] - pscore[b * MM + m]);

    g_score[idx] = sc;
    g_box[idx] = bcost;
    g_cost[idx] = sc + bcost;
}

// ---------------------------------------------------------------------------
// Kernel 2: Hungarian (JV / e-maxx) — one warp per batch.
// Lane l owns columns j = l*8+1 .. l*8+8 (1-based). Doubles mirror the
// reference float64 solver; argmin tie-break = smallest index (np.argmin).
// ---------------------------------------------------------------------------
__global__ void lsa_kernel(float* __restrict__ out) {
    const int b = blockIdx.x;
    const int lane = threadIdx.x;  // 0..31
    const float* C = g_cost + b * MAT;

    __shared__ double u_s[MM + 1];
    __shared__ int p_s[MM + 1];
    __shared__ int way_s[MM + 1];

    for (int j = lane; j <= MM; j += 32) { u_s[j] = 0.0; p_s[j] = 0; way_s[j] = 0; }
    double v_r[8];
#pragma unroll
    for (int k = 0; k < 8; k++) v_r[k] = 0.0;
    __syncwarp();

    const double INF = 1e30;

    for (int i = 1; i <= MM; i++) {
        if (lane == 0) p_s[0] = i;
        double minv_r[8];
#pragma unroll
        for (int k = 0; k < 8; k++) minv_r[k] = INF;
        unsigned usedmask = 0;
        bool used0 = false;
        __syncwarp();

        int j0 = 0;
        while (true) {
            // used[j0] = true
            if (j0 == 0) used0 = true;
            else if (lane == ((j0 - 1) >> 3)) usedmask |= 1u << ((j0 - 1) & 7);

            const int i0 = p_s[j0];
            const double u_i0 = u_s[i0];
            const float* row = C + (i0 - 1) * MM;

            double bestv = INF;
            int bestj = MM + 1;
#pragma unroll
            for (int k = 0; k < 8; k++) {
                const int j = lane * 8 + k + 1;
                if (!(usedmask & (1u << k))) {
                    const double cur = (double)row[j - 1] - u_i0 - v_r[k];
                    if (cur < minv_r[k]) { minv_r[k] = cur; way_s[j] = j0; }
                    if (minv_r[k] < bestv) { bestv = minv_r[k]; bestj = j; }
                }
            }
            // warp argmin with first-index tie-break
#pragma unroll
            for (int off = 16; off; off >>= 1) {
                const double ov = __shfl_xor_sync(0xffffffffu, bestv, off);
                const int oj = __shfl_xor_sync(0xffffffffu, bestj, off);
                if (ov < bestv || (ov == bestv && oj < bestj)) { bestv = ov; bestj = oj; }
            }
            const double delta = bestv;
            const int j0n = bestj;

            // dual updates: old used-set gets delta; free columns' minv shrink
#pragma unroll
            for (int k = 0; k < 8; k++) {
                const int j = lane * 8 + k + 1;
                if (usedmask & (1u << k)) {
                    v_r[k] -= delta;
                    u_s[p_s[j]] += delta;  // distinct rows across used cols
                } else {
                    minv_r[k] -= delta;
                }
            }
            if (lane == 0 && used0) u_s[p_s[0]] += delta;  // column 0 -> row i
            __syncwarp();

            j0 = j0n;
            if (p_s[j0] == 0) break;
        }

        __syncwarp();
        if (lane == 0) {  // augment along the alternating path
            int jj = j0;
            while (jj != 0) {
                const int j1 = way_s[jj];
                p_s[jj] = p_s[j1];
                jj = j1;
            }
        }
        __syncwarp();
    }

    // matched sums: row p_s[j]-1 <-> col j-1
    const float* S = g_score + b * MAT;
    const float* Bx = g_box + b * MAT;
    double sc = 0.0, ss = 0.0, sb = 0.0;
    for (int j = lane + 1; j <= MM; j += 32) {
        const int r = p_s[j] - 1;
        const int c = j - 1;
        sc += (double)C[r * MM + c];
        ss += (double)S[r * MM + c];
        sb += (double)Bx[r * MM + c];
    }
#pragma unroll
    for (int off = 16; off; off >>= 1) {
        sc += __shfl_xor_sync(0xffffffffu, sc, off);
        ss += __shfl_xor_sync(0xffffffffu, ss, off);
        sb += __shfl_xor_sync(0xffffffffu, sb, off);
    }
    if (lane == 0) {
        out[0 * BB + b] = (float)(sc / (double)NT);
        out[1 * BB + b] = (float)(ss / (double)NT);
        out[2 * BB + b] = (float)(sb / (double)NT);
    }
}

extern "C" void kernel_launch(void* const* d_in, const int* in_sizes, int n_in,
                              void* d_out, int out_size) {
    const float* pbox   = (const float*)d_in[0];  // [B,M,5]
    const float* pscore = (const float*)d_in[1];  // [B,M]
    const float* tbox   = (const float*)d_in[2];  // [B,N,5]
    const float* tscore = (const float*)d_in[3];  // [B,N]
    float* out = (float*)d_out;                   // [3,B]

    cost_kernel<<<(BB * MAT + 255) / 256, 256>>>(pbox, pscore, tbox, tscore);
    lsa_kernel<<<BB, 32>>>(out);
}

// round 7
// speedup vs baseline: 8.8030x; 8.8030x over previous
#include <cuda_runtime.h>

// Problem constants (fixed by dataset): B=4, M=256 preds, N=192 targets.
#define BB 4
#define MM 256
#define NT 192
#define MAT (MM * MM)

// Scratch (static __device__ — no allocations allowed)
__device__ float g_cost[BB * MAT];
__device__ float g_score[BB * MAT];
__device__ float g_box[BB * MAT];

// ---------------------------------------------------------------------------
// Kernel 1: cost matrices. One thread per (b, m, n_full), n_full in [0,256)
// ---------------------------------------------------------------------------
__device__ __forceinline__ void box_corners(const float* __restrict__ box,
                                            float* X, float* Y) {
    const float cx = box[0], cy = box[1], w = box[2], h = box[3], th = box[4];
    const float c = cosf(th), s = sinf(th);
    const float hw = 0.5f * w, hh = 0.5f * h;
    const float dx[4] = {-hw, hw, hw, -hw};
    const float dy[4] = {-hh, -hh, hh, hh};
#pragma unroll
    for (int k = 0; k < 4; k++) {
        X[k] = cx + dx[k] * c - dy[k] * s;
        Y[k] = cy + dx[k] * s + dy[k] * c;
    }
}

__global__ void cost_kernel(const float* __restrict__ pbox,
                            const float* __restrict__ pscore,
                            const float* __restrict__ tbox,
                            const float* __restrict__ tscore) {
    const int idx = blockIdx.x * 256 + threadIdx.x;
    if (idx >= BB * MAT) return;
    const int n = idx & (MM - 1);
    const int m = (idx >> 8) & (MM - 1);
    const int b = idx >> 16;

    if (n >= NT) {  // zero padding columns
        g_cost[idx] = 0.f; g_score[idx] = 0.f; g_box[idx] = 0.f;
        return;
    }

    const float* bp = pbox + (b * MM + m) * 5;   // pred box
    const float* bt = tbox + (b * NT + n) * 5;   // target box

    float cpx[4], cpy[4], ctx_[4], cty_[4];
    box_corners(bp, cpx, cpy);   // pred corners (polygon to clip)
    box_corners(bt, ctx_, cty_); // target corners (clip edges)

    // Sutherland-Hodgman: clip pred quad by 4 target edges (keep left side)
    float px[8], py[8], qx[8], qy[8];
    int cnt = 4;
#pragma unroll
    for (int k = 0; k < 4; k++) { px[k] = cpx[k]; py[k] = cpy[k]; }

    for (int e = 0; e < 4; e++) {
        const float ax = ctx_[e], ay = cty_[e];
        const float bx = ctx_[(e + 1) & 3], by = cty_[(e + 1) & 3];
        const float dx = bx - ax, dy = by - ay;
        int m2 = 0;
        for (int k = 0; k < cnt; k++) {
            const int kn = (k + 1 == cnt) ? 0 : k + 1;
            const float cxk = px[k], cyk = py[k];
            const float nxk = px[kn], nyk = py[kn];
            const float s_cur = dx * (cyk - ay) - dy * (cxk - ax);
            const float s_nxt = dx * (nyk - ay) - dy * (nxk - ax);
            const bool in_cur = (s_cur >= 0.f);
            const bool in_nxt = (s_nxt >= 0.f);
            if (in_cur) { qx[m2] = cxk; qy[m2] = cyk; m2++; }
            if (in_cur != in_nxt) {
                float den = s_cur - s_nxt;
                if (fabsf(den) <= 1e-9f) den = 1e-9f;
                const float t = s_cur / den;
                qx[m2] = cxk + t * (nxk - cxk);
                qy[m2] = cyk + t * (nyk - cyk);
                m2++;
            }
        }
        cnt = m2;
        for (int k = 0; k < cnt; k++) { px[k] = qx[k]; py[k] = qy[k]; }
    }

    float acc = 0.f;
    for (int k = 0; k < cnt; k++) {
        const int kn = (k + 1 == cnt) ? 0 : k + 1;
        acc += px[k] * py[kn] - px[kn] * py[k];
    }
    const float inter = 0.5f * fabsf(acc);

    const float uni = bt[2] * bt[3] + bp[2] * bp[3] - inter;

    float xmin = cpx[0], xmax = cpx[0], ymin = cpy[0], ymax = cpy[0];
#pragma unroll
    for (int k = 0; k < 4; k++) {
        xmin = fminf(xmin, cpx[k]); xmax = fmaxf(xmax, cpx[k]);
        ymin = fminf(ymin, cpy[k]); ymax = fmaxf(ymax, cpy[k]);
        xmin = fminf(xmin, ctx_[k]); xmax = fmaxf(xmax, ctx_[k]);
        ymin = fminf(ymin, cty_[k]); ymax = fmaxf(ymax, cty_[k]);
    }
    const float enc = (xmax - xmin) * (ymax - ymin);
    const float giou = inter / uni - (enc - uni) / enc;
    const float bcost = 1.f - giou;

    const float sc = fmaxf(0.f, tscore[b * NT + n] - pscore[b * MM + m]);

    g_score[idx] = sc;
    g_box[idx] = bcost;
    g_cost[idx] = sc + bcost;
}

// ---------------------------------------------------------------------------
// Kernel 2: Jonker-Volgenant LSAP — one 256-thread block per batch.
// Thread j owns column j (Dijkstra phase) / row j (greedy phase).
// Duals & dists in fp64 for exactness; all reductions use int64 compares
// (valid: values >= 0, so IEEE double order == int64 order).
// ---------------------------------------------------------------------------
#define LLINF 0x7FE0000000000000LL  // huge positive double as int64

// Block argmin of (key, j). One __syncthreads; parity double-buffers slots.
__device__ __forceinline__ void block_argmin(long long key, int jj, int parity,
                                             volatile long long* red_v,
                                             volatile int* red_j,
                                             long long& out_key, int& out_j) {
#pragma unroll
    for (int off = 16; off; off >>= 1) {
        long long ok = __shfl_xor_sync(0xffffffffu, key, off);
        int oj = __shfl_xor_sync(0xffffffffu, jj, off);
        if (ok < key || (ok == key && oj < jj)) { key = ok; jj = oj; }
    }
    const int w = threadIdx.x >> 5;
    const int base = parity * 8;
    if ((threadIdx.x & 31) == 0) { red_v[base + w] = key; red_j[base + w] = jj; }
    __syncthreads();
    long long bk = red_v[base]; int bj = red_j[base];
#pragma unroll
    for (int t = 1; t < 8; t++) {
        long long ok = red_v[base + t]; int oj = red_j[base + t];
        if (ok < bk || (ok == bk && oj < bj)) { bk = ok; bj = oj; }
    }
    out_key = bk; out_j = bj;
}

__global__ __launch_bounds__(256, 1) void lsa_kernel(float* __restrict__ out) {
    const int b = blockIdx.x;
    const int j = threadIdx.x;
    const float* __restrict__ C = g_cost + b * MAT;

    __shared__ double v_s[MM];
    __shared__ int y_s[MM];     // column -> row (-1 = free)
    __shared__ int way_s[MM];   // predecessor column on SP tree
    __shared__ int bestj_s[MM]; // row -> argmin column (greedy)
    __shared__ long long red_v[16];
    __shared__ int red_j[16];
    __shared__ int free_s[MM];
    __shared__ int nfree_s;
    __shared__ double acc_s[3];

    // ---- init: v[j] = min_i C[i][j] (column reduction) ----
    {
        long long m0 = LLINF, m1 = LLINF, m2 = LLINF, m3 = LLINF;
#pragma unroll 4
        for (int i = 0; i < MM; i += 4) {  // costs >= 0 -> int64 min is exact
            long long t0 = __double_as_longlong((double)__ldg(&C[(i + 0) * MM + j]));
            long long t1 = __double_as_longlong((double)__ldg(&C[(i + 1) * MM + j]));
            long long t2 = __double_as_longlong((double)__ldg(&C[(i + 2) * MM + j]));
            long long t3 = __double_as_longlong((double)__ldg(&C[(i + 3) * MM + j]));
            m0 = min(m0, t0); m1 = min(m1, t1); m2 = min(m2, t2); m3 = min(m3, t3);
        }
        v_s[j] = __longlong_as_double(min(min(m0, m1), min(m2, m3)));
    }
    y_s[j] = -1;
    if (j == 0) { nfree_s = 0; acc_s[0] = acc_s[1] = acc_s[2] = 0.0; }
    __syncthreads();
    int parity = 0;

    // ---- greedy: thread j = row j; find argmin_c (C[j][c] - v[c]) ----
    {
        long long best = LLINF; int bj = 0;
        const float* row = C + j * MM;
        for (int c = 0; c < MM; c++) {
            const double t = (double)__ldg(&row[c]) - v_s[c];  // >= 0
            const long long kb = __double_as_longlong(t);
            if (kb < best) { best = kb; bj = c; }  // first-index tie-break
        }
        bestj_s[j] = bj;
    }
    __syncthreads();
    if (j == 0) {
        // resolve conflicts; losers absorb free PAD columns (any row is
        // dual-tight on a pad column: C=0, v=0 => u=0 feasible post col-red)
        int np = NT;  // next candidate pad column
        for (int i = 0; i < MM; i++) {
            const int c = bestj_s[i];
            if (y_s[c] < 0) { y_s[c] = i; continue; }
            while (np < MM && y_s[np] >= 0) np++;
            if (np < MM) y_s[np++] = i;
            else free_s[nfree_s++] = i;
        }
    }
    __syncthreads();
    const int nf = nfree_s;

    // ---- augment each free row via Dijkstra shortest alternating path ----
    for (int fi = 0; fi < nf; fi++) {
        const int f = free_s[fi];
        double d = (double)__ldg(&C[f * MM + j]) - v_s[j];
        int way = -1;
        bool used = false;
        int jmin = 0; double mu = 0.0;

        // Bounded: each pass marks a new column used; <= MM passes. Guard is
        // semantics-neutral insurance against an unmodeled livelock (finite
        // wrong answer beats a harness hang with zero signal).
        for (int it = 0; it <= MM; it++) {
            const long long key = used ? LLINF : __double_as_longlong(d);
            long long mk; int mj;
            block_argmin(key, j, parity, red_v, red_j, mk, mj);
            parity ^= 1;
            jmin = mj;
            mu = __longlong_as_double(mk);
            if (j == jmin) used = true;
            const int i0 = y_s[jmin];
            if (i0 < 0) break;  // free column reached -> augment
            // implicit u[i0] = C[i0][jmin] - v[jmin] (CS on assigned arcs)
            const double ui = (double)__ldg(&C[i0 * MM + jmin]) - v_s[jmin];
            if (!used) {
                const double t = (double)__ldg(&C[i0 * MM + j]) - v_s[j];
                const double nd = (mu - ui) + t;
                if (nd < d) { d = nd; way = jmin; }
            }
        }

        // dual update (scanned columns except endpoint) + publish way
        if (used) {
            way_s[j] = way;
            if (j != jmin) v_s[j] += d - mu;
        }
        __syncthreads();
        if (j == 0) {  // walk the alternating path, flip assignment
            int jj = jmin;
            for (int it = 0; it <= MM; it++) {  // bounded: way chain acyclic
                const int pj = way_s[jj];
                const int i = (pj < 0) ? f : y_s[pj];
                y_s[jj] = i;
                if (pj < 0) break;
                jj = pj;
            }
        }
        __syncthreads();
    }

    // ---- matched sums: column j <-> row y_s[j] ----
    const float* __restrict__ S = g_score + b * MAT;
    const float* __restrict__ Bx = g_box + b * MAT;
    const int r = max(y_s[j], 0);
    double sc = (double)__ldg(&C[r * MM + j]);
    double ss = (double)__ldg(&S[r * MM + j]);
    double sb = (double)__ldg(&Bx[r * MM + j]);
#pragma unroll
    for (int off = 16; off; off >>= 1) {
        sc += __shfl_xor_sync(0xffffffffu, sc, off);
        ss += __shfl_xor_sync(0xffffffffu, ss, off);
        sb += __shfl_xor_sync(0xffffffffu, sb, off);
    }
    if ((j & 31) == 0) {
        atomicAdd(&acc_s[0], sc);
        atomicAdd(&acc_s[1], ss);
        atomicAdd(&acc_s[2], sb);
    }
    __syncthreads();
    if (j == 0) {
        out[0 * BB + b] = (float)(acc_s[0] / (double)NT);
        out[1 * BB + b] = (float)(acc_s[1] / (double)NT);
        out[2 * BB + b] = (float)(acc_s[2] / (double)NT);
    }
}

extern "C" void kernel_launch(void* const* d_in, const int* in_sizes, int n_in,
                              void* d_out, int out_size) {
    const float* pbox   = (const float*)d_in[0];  // [B,M,5]
    const float* pscore = (const float*)d_in[1];  // [B,M]
    const float* tbox   = (const float*)d_in[2];  // [B,N,5]
    const float* tscore = (const float*)d_in[3];  // [B,N]
    float* out = (float*)d_out;                   // [3,B]

    cost_kernel<<<(BB * MAT + 255) / 256, 256>>>(pbox, pscore, tbox, tscore);
    lsa_kernel<<<BB, 256>>>(out);
}

// round 10
// speedup vs baseline: 9.3273x; 1.0596x over previous
#include <cuda_runtime.h>

// Problem constants (fixed by dataset): B=4, M=256 preds, N=192 targets.
#define BB 4
#define MM 256
#define NT 192
#define MAT (MM * MM)
#define CSTRIDE 193            // smem row stride (floats); 193%32==1 -> conflict-free both ways
#define QSCALE 1099511627776.f // 2^40 (exact float scale: exponent shift only)
#define SENT 0x7FFFFFFFFFFFFFFFLL
#define SMEM_BYTES (MM * CSTRIDE * 4)

// Scratch (static __device__ — no allocations allowed)
__device__ float g_cost[BB * MAT];
__device__ float g_score[BB * MAT];
__device__ float g_box[BB * MAT];

// ---------------------------------------------------------------------------
// Kernel 1: cost matrices. One thread per (b, m, n_full), n_full in [0,256)
// ---------------------------------------------------------------------------
__device__ __forceinline__ void box_corners(const float* __restrict__ box,
                                            float* X, float* Y) {
    const float cx = box[0], cy = box[1], w = box[2], h = box[3], th = box[4];
    const float c = cosf(th), s = sinf(th);
    const float hw = 0.5f * w, hh = 0.5f * h;
    const float dx[4] = {-hw, hw, hw, -hw};
    const float dy[4] = {-hh, -hh, hh, hh};
#pragma unroll
    for (int k = 0; k < 4; k++) {
        X[k] = cx + dx[k] * c - dy[k] * s;
        Y[k] = cy + dx[k] * s + dy[k] * c;
    }
}

__global__ void cost_kernel(const float* __restrict__ pbox,
                            const float* __restrict__ pscore,
                            const float* __restrict__ tbox,
                            const float* __restrict__ tscore) {
    const int idx = blockIdx.x * 256 + threadIdx.x;
    if (idx >= BB * MAT) return;
    const int n = idx & (MM - 1);
    const int m = (idx >> 8) & (MM - 1);
    const int b = idx >> 16;

    if (n >= NT) {  // zero padding columns
        g_cost[idx] = 0.f; g_score[idx] = 0.f; g_box[idx] = 0.f;
        return;
    }

    const float* bp = pbox + (b * MM + m) * 5;   // pred box
    const float* bt = tbox + (b * NT + n) * 5;   // target box

    float cpx[4], cpy[4], ctx_[4], cty_[4];
    box_corners(bp, cpx, cpy);   // pred corners (polygon to clip)
    box_corners(bt, ctx_, cty_); // target corners (clip edges)

    // Sutherland-Hodgman: clip pred quad by 4 target edges (keep left side)
    float px[8], py[8], qx[8], qy[8];
    int cnt = 4;
#pragma unroll
    for (int k = 0; k < 4; k++) { px[k] = cpx[k]; py[k] = cpy[k]; }

    for (int e = 0; e < 4; e++) {
        const float ax = ctx_[e], ay = cty_[e];
        const float bx = ctx_[(e + 1) & 3], by = cty_[(e + 1) & 3];
        const float dx = bx - ax, dy = by - ay;
        int m2 = 0;
        for (int k = 0; k < cnt; k++) {
            const int kn = (k + 1 == cnt) ? 0 : k + 1;
            const float cxk = px[k], cyk = py[k];
            const float nxk = px[kn], nyk = py[kn];
            const float s_cur = dx * (cyk - ay) - dy * (cxk - ax);
            const float s_nxt = dx * (nyk - ay) - dy * (nxk - ax);
            const bool in_cur = (s_cur >= 0.f);
            const bool in_nxt = (s_nxt >= 0.f);
            if (in_cur) { qx[m2] = cxk; qy[m2] = cyk; m2++; }
            if (in_cur != in_nxt) {
                float den = s_cur - s_nxt;
                if (fabsf(den) <= 1e-9f) den = 1e-9f;
                const float t = s_cur / den;
                qx[m2] = cxk + t * (nxk - cxk);
                qy[m2] = cyk + t * (nyk - cyk);
                m2++;
            }
        }
        cnt = m2;
        for (int k = 0; k < cnt; k++) { px[k] = qx[k]; py[k] = qy[k]; }
    }

    float acc = 0.f;
    for (int k = 0; k < cnt; k++) {
        const int kn = (k + 1 == cnt) ? 0 : k + 1;
        acc += px[k] * py[kn] - px[kn] * py[k];
    }
    const float inter = 0.5f * fabsf(acc);

    const float uni = bt[2] * bt[3] + bp[2] * bp[3] - inter;

    float xmin = cpx[0], xmax = cpx[0], ymin = cpy[0], ymax = cpy[0];
#pragma unroll
    for (int k = 0; k < 4; k++) {
        xmin = fminf(xmin, cpx[k]); xmax = fmaxf(xmax, cpx[k]);
        ymin = fminf(ymin, cpy[k]); ymax = fmaxf(ymax, cpy[k]);
        xmin = fminf(xmin, ctx_[k]); xmax = fmaxf(xmax, ctx_[k]);
        ymin = fminf(ymin, cty_[k]); ymax = fmaxf(ymax, cty_[k]);
    }
    const float enc = (xmax - xmin) * (ymax - ymin);
    const float giou = inter / uni - (enc - uni) / enc;
    const float bcost = 1.f - giou;

    const float sc = fmaxf(0.f, tscore[b * NT + n] - pscore[b * MM + m]);

    g_score[idx] = sc;
    g_box[idx] = bcost;
    g_cost[idx] = sc + bcost;
}

// ---------------------------------------------------------------------------
// Kernel 2: Jonker-Volgenant LSAP, int64 fixed-point (scale 2^40).
// One block of 256 threads per batch. Prep phases (smem fill, column
// reduction, greedy) use all 256 threads; the serial Dijkstra runs on
// warp 0 only (8 columns/lane), barrier-free, with a packed (dist<<9)|j
// key so a single shuffle-min gives argmin + first-index tie-break.
// Quantization at 2^-40 perturbs any assignment total by <= 2.3e-10:
// below any generic optimum gap, so the assignment equals the exact one.
// ---------------------------------------------------------------------------
// Cs holds cost*2^40 as float (exact: exponent shift). Pad cols implicit 0.
__device__ __forceinline__ long long qc(const float* Cs, int i, int j) {
    const float c = (j < NT) ? Cs[i * CSTRIDE + j] : 0.f;
    return __float2ll_rz(c);  // deterministic truncation = the quantizer
}

__global__ __launch_bounds__(256, 1) void lsa_kernel(float* __restrict__ out) {
    extern __shared__ float Cs[];  // [MM][CSTRIDE], pre-scaled by 2^40
    const int b = blockIdx.x;
    const int j = threadIdx.x;
    const int lane = j & 31;
    const float* __restrict__ G = g_cost + b * MAT;

    __shared__ long long v_s[MM];  // column duals (fixed-point)
    __shared__ int y_s[MM];        // column -> row (-1 = free)
    __shared__ int way_s[MM];      // predecessor column on SP tree
    __shared__ int bestj_s[MM];    // row -> argmin column (greedy)
    __shared__ int free_s[MM];
    __shared__ int nfree_s;
    __shared__ double acc_s[3];

    // ---- fill smem with scaled costs (coalesced) ----
    for (int idx = j; idx < MM * NT; idx += 256) {
        const int r = idx / NT, c = idx - r * NT;
        Cs[r * CSTRIDE + c] = G[r * MM + c] * QSCALE;
    }
    if (j == 0) { nfree_s = 0; acc_s[0] = acc_s[1] = acc_s[2] = 0.0; }
    __syncthreads();

    // ---- column reduction: v[j] = min_i q[i][j] ----
    {
        long long m0 = SENT, m1 = SENT;
#pragma unroll 2
        for (int i = 0; i < MM; i += 2) {
            m0 = min(m0, qc(Cs, i + 0, j));
            m1 = min(m1, qc(Cs, i + 1, j));
        }
        v_s[j] = min(m0, m1);  // pads: all-zero column -> v = 0
    }
    y_s[j] = -1;
    __syncthreads();

    // ---- greedy: thread j = row j; packed argmin_c (q[j][c] - v[c]) ----
    {
        long long best = SENT;
        for (int c = 0; c < MM; c++) {
            const long long t = qc(Cs, j, c) - v_s[c];
            best = min(best, (t << 9) | (long long)c);
        }
        bestj_s[j] = (int)(best & 511);
    }
    __syncthreads();
    if (j == 0) {
        // resolve conflicts; losers absorb free PAD columns (dual-tight:
        // q=0, v[pad]=0 => u=0 feasible after column reduction)
        int np = NT;
        for (int i = 0; i < MM; i++) {
            const int c = bestj_s[i];
            if (y_s[c] < 0) { y_s[c] = i; continue; }
            while (np < MM && y_s[np] >= 0) np++;
            if (np < MM) y_s[np++] = i;
            else free_s[nfree_s++] = i;
        }
    }
    __syncthreads();
    const int nf = nfree_s;

    // ---- Dijkstra augmentation: warp 0 only, 8 columns per lane ----
    if (j < 32) {
        for (int fi = 0; fi < nf; fi++) {
            const int f = free_s[fi];
            long long d[8];
            int way[8];
#pragma unroll
            for (int k = 0; k < 8; k++) {
                const int jj = lane * 8 + k;
                d[k] = qc(Cs, f, jj) - v_s[jj];
                way[k] = -1;
            }
            unsigned usedmask = 0;
            int jmin = 0;
            long long mu = 0;

            // each pass marks a new column used -> <= MM passes (guard kept
            // as semantics-neutral hang insurance)
            for (int it = 0; it <= MM; it++) {
                long long best = SENT;
#pragma unroll
                for (int k = 0; k < 8; k++) {
                    if (!(usedmask & (1u << k))) {
                        const long long key =
                            (d[k] << 9) | (long long)(lane * 8 + k);
                        best = min(best, key);
                    }
                }
#pragma unroll
                for (int off = 16; off; off >>= 1)
                    best = min(best, __shfl_xor_sync(0xffffffffu, best, off));
                jmin = (int)(best & 511);
                mu = best >> 9;
                if (lane == (jmin >> 3)) usedmask |= 1u << (jmin & 7);

                const int i0 = y_s[jmin];
                if (i0 < 0) break;  // free column reached -> augment
                // implicit u[i0] = q[i0][jmin] - v[jmin]
                const long long base = mu - (qc(Cs, i0, jmin) - v_s[jmin]);
#pragma unroll
                for (int k = 0; k < 8; k++) {
                    if (!(usedmask & (1u << k))) {
                        const int jj = lane * 8 + k;
                        const long long nd = base + qc(Cs, i0, jj) - v_s[jj];
                        if (nd < d[k]) { d[k] = nd; way[k] = jmin; }
                    }
                }
            }

            // dual update (scanned cols except endpoint) + publish way
#pragma unroll
            for (int k = 0; k < 8; k++) {
                if (usedmask & (1u << k)) {
                    const int jj = lane * 8 + k;
                    way_s[jj] = way[k];
                    if (jj != jmin) v_s[jj] += d[k] - mu;
                }
            }
            __syncwarp();
            if (lane == 0) {  // walk the alternating path, flip assignment
                int jj = jmin;
                for (int it = 0; it <= MM; it++) {  // way chain is acyclic
                    const int pj = way_s[jj];
                    const int i = (pj < 0) ? f : y_s[pj];
                    y_s[jj] = i;
                    if (pj < 0) break;
                    jj = pj;
                }
            }
            __syncwarp();
        }
    }
    __syncthreads();  // warps 1-7 wait here while warp 0 solves

    // ---- matched sums: column j <-> row y_s[j] (exact fp64 from fp32) ----
    const float* __restrict__ S = g_score + b * MAT;
    const float* __restrict__ Bx = g_box + b * MAT;
    const int r = max(y_s[j], 0);
    double sc = (double)__ldg(&G[r * MM + j]);
    double ss = (double)__ldg(&S[r * MM + j]);
    double sb = (double)__ldg(&Bx[r * MM + j]);
#pragma unroll
    for (int off = 16; off; off >>= 1) {
        sc += __shfl_xor_sync(0xffffffffu, sc, off);
        ss += __shfl_xor_sync(0xffffffffu, ss, off);
        sb += __shfl_xor_sync(0xffffffffu, sb, off);
    }
    if (lane == 0) {
        atomicAdd(&acc_s[0], sc);
        atomicAdd(&acc_s[1], ss);
        atomicAdd(&acc_s[2], sb);
    }
    __syncthreads();
    if (j == 0) {
        out[0 * BB + b] = (float)(acc_s[0] / (double)NT);
        out[1 * BB + b] = (float)(acc_s[1] / (double)NT);
        out[2 * BB + b] = (float)(acc_s[2] / (double)NT);
    }
}

extern "C" void kernel_launch(void* const* d_in, const int* in_sizes, int n_in,
                              void* d_out, int out_size) {
    const float* pbox   = (const float*)d_in[0];  // [B,M,5]
    const float* pscore = (const float*)d_in[1];  // [B,M]
    const float* tbox   = (const float*)d_in[2];  // [B,N,5]
    const float* tscore = (const float*)d_in[3];  // [B,N]
    float* out = (float*)d_out;                   // [3,B]

    // Unconditional (no static state): idempotent, capture-legal attribute.
    cudaFuncSetAttribute(lsa_kernel,
                         cudaFuncAttributeMaxDynamicSharedMemorySize,
                         SMEM_BYTES);

    cost_kernel<<<(BB * MAT + 255) / 256, 256>>>(pbox, pscore, tbox, tscore);
    lsa_kernel<<<BB, 256, SMEM_BYTES>>>(out);
}